// round 11
// baseline (speedup 1.0000x reference)
#include <cuda_runtime.h>
#include <cuda_bf16.h>
#include <mma.h>

using namespace nvcuda;
typedef __nv_bfloat16 bf16;

#define CC   128
#define NB   9
#define RPD  8
#define HID  128
#define NTOK 32768
#define TPB  32          // tokens per main block
#define MROW (TPB*NB)    // 288 edge rows
#define WS   272         // Wcat bf16 stride (cols 0-127 drive, 128-255 resist)

// ---- device scratch (no runtime allocation) ----
__device__ bf16  g_normbf[NTOK*CC];
__device__ float g_cd[NTOK*HID];
__device__ float g_cr[NTOK*HID];
__device__ bf16  g_Ad[CC*HID], g_Ar[CC*HID];   // Wn - Wd
__device__ bf16  g_Bd[CC*HID], g_Br[CC*HID];   // Wc + Wd
__device__ bf16  g_vWb[CC*CC], g_oWb[CC*CC];
__device__ float g_relbd[NB*HID], g_relbr[NB*HID];
__device__ float g_vbo[CC];                     // vb @ oW

__device__ __forceinline__ float gelu_fast(float x) {
    float u = 0.7978845608f * x * (1.0f + 0.044715f * x * x);
    float t;
    asm("tanh.approx.f32 %0, %1;" : "=f"(t) : "f"(u));
    return 0.5f * x * (1.0f + t);
}

// ================= kernel 0: fold weights, rel-bias tables, vbo =================
__global__ void k_prep(const float* __restrict__ dW1, const float* __restrict__ rW1,
                       const float* __restrict__ vW,  const float* __restrict__ oW,
                       const float* __restrict__ rel_pos,
                       const float* __restrict__ db1, const float* __restrict__ rb1,
                       const float* __restrict__ vb)
{
    int i = blockIdx.x * blockDim.x + threadIdx.x;
    if (i >= CC*HID) return;
    int c = i >> 7, h = i & 127;
    g_Ad[i] = __float2bfloat16(dW1[(CC+c)*HID+h]   - dW1[(2*CC+c)*HID+h]);
    g_Bd[i] = __float2bfloat16(dW1[c*HID+h]        + dW1[(2*CC+c)*HID+h]);
    g_Ar[i] = __float2bfloat16(rW1[(CC+c)*HID+h]   - rW1[(2*CC+c)*HID+h]);
    g_Br[i] = __float2bfloat16(rW1[c*HID+h]        + rW1[(2*CC+c)*HID+h]);
    g_vWb[i] = __float2bfloat16(vW[i]);
    g_oWb[i] = __float2bfloat16(oW[i]);
    if (i < NB*HID) {
        int n = i >> 7;
        float sd = db1[h], sr = rb1[h];
        #pragma unroll
        for (int r = 0; r < RPD; r++) {
            float rp = rel_pos[n*RPD + r];
            sd += rp * dW1[(3*CC+r)*HID+h];
            sr += rp * rW1[(3*CC+r)*HID+h];
        }
        g_relbd[i] = sd; g_relbr[i] = sr;
    }
    if (i < CC) {
        float s = 0.f;
        for (int c2 = 0; c2 < CC; c2++) s += vb[c2] * oW[c2*CC + i];
        g_vbo[i] = s;
    }
}

// ================= kernel 1: LayerNorm1 -> bf16 =================
__global__ void k_ln1(const float* __restrict__ tokens,
                      const float* __restrict__ g, const float* __restrict__ b)
{
    int wid = threadIdx.x >> 5, lane = threadIdx.x & 31;
    int row = blockIdx.x * 8 + wid;
    float4 v = reinterpret_cast<const float4*>(tokens + (size_t)row*CC)[lane];
    float s = v.x + v.y + v.z + v.w;
    #pragma unroll
    for (int o = 16; o; o >>= 1) s += __shfl_xor_sync(0xffffffffu, s, o);
    float mean = s * (1.0f/128.0f);
    float d0=v.x-mean, d1=v.y-mean, d2=v.z-mean, d3=v.w-mean;
    float q = d0*d0+d1*d1+d2*d2+d3*d3;
    #pragma unroll
    for (int o = 16; o; o >>= 1) q += __shfl_xor_sync(0xffffffffu, q, o);
    float rstd = rsqrtf(q * (1.0f/128.0f) + 1e-5f);
    float4 gg = reinterpret_cast<const float4*>(g)[lane];
    float4 bb = reinterpret_cast<const float4*>(b)[lane];
    __nv_bfloat162 p0 = __floats2bfloat162_rn(d0*rstd*gg.x+bb.x, d1*rstd*gg.y+bb.y);
    __nv_bfloat162 p1 = __floats2bfloat162_rn(d2*rstd*gg.z+bb.z, d3*rstd*gg.w+bb.w);
    uint2 pk; pk.x = *reinterpret_cast<unsigned int*>(&p0); pk.y = *reinterpret_cast<unsigned int*>(&p1);
    reinterpret_cast<uint2*>(g_normbf + (size_t)row*CC)[lane] = pk;
}

// ================= kernel 2: center GEMMs (split drive/resist by blockIdx.y) =========
#define CSMEM (2*128*136*2)
__global__ void __launch_bounds__(256) k_center()
{
    extern __shared__ char sm[];
    bf16* Xs = reinterpret_cast<bf16*>(sm);
    bf16* Ws = Xs + 128*136;
    int tid = threadIdx.x, wid = tid >> 5;
    int row0 = blockIdx.x * 128;
    int which = blockIdx.y;
    const bf16* Wg = which ? g_Br : g_Bd;
    float* outg = which ? g_cr : g_cd;
    for (int i = tid; i < 8192; i += 256) {
        int r = i >> 6, c = i & 63;
        reinterpret_cast<unsigned int*>(Ws)[r*68+c] = reinterpret_cast<const unsigned int*>(Wg)[i];
        reinterpret_cast<unsigned int*>(Xs)[r*68+c] =
            reinterpret_cast<const unsigned int*>(g_normbf + (size_t)row0*CC)[i];
    }
    __syncthreads();
    wmma::fragment<wmma::matrix_a,16,16,16,bf16,wmma::row_major> fa;
    wmma::fragment<wmma::matrix_b,16,16,16,bf16,wmma::row_major> fb;
    wmma::fragment<wmma::accumulator,16,16,16,float> acc[8];
    #pragma unroll
    for (int ct = 0; ct < 8; ct++) wmma::fill_fragment(acc[ct], 0.0f);
    for (int kt = 0; kt < 8; kt++) {
        wmma::load_matrix_sync(fa, Xs + wid*16*136 + kt*16, 136);
        #pragma unroll
        for (int ct = 0; ct < 8; ct++) {
            wmma::load_matrix_sync(fb, Ws + kt*16*136 + ct*16, 136);
            wmma::mma_sync(acc[ct], fa, fb, acc[ct]);
        }
    }
    #pragma unroll
    for (int ct = 0; ct < 8; ct++)
        wmma::store_matrix_sync(outg + (size_t)(row0+wid*16)*HID + ct*16, acc[ct], HID, wmma::mem_row_major);
}

// ================= main fused kernel =================
struct SmemMain {
    bf16 Wcat[128*WS];            // 69.6 KB
    bf16 Vs[MROW*136];            // 78.3 KB (later aliased by msg/Us)
    bf16 mv[TPB*136];             // 8.7 KB
    float Cds[TPB*132], Crs[TPB*132];   // 33.8 KB
    float relbd[NB*132], relbr[NB*132]; // 9.5 KB
    float w2d[128], w2r[128];
    float drive[MROW], resist[MROW], gate[MROW];
    float gsum[TPB], invm[TPB];
};

__global__ void __launch_bounds__(576, 1) k_main(
    const float* __restrict__ tokens,
    const float* __restrict__ ln2g, const float* __restrict__ ln2b,
    const float* __restrict__ dW2,  const float* __restrict__ db2,
    const float* __restrict__ rW2,  const float* __restrict__ rb2,
    const float* __restrict__ ob,
    const float* __restrict__ pg, const float* __restrict__ pl, const float* __restrict__ pb,
    float* __restrict__ out)
{
    extern __shared__ char smraw[];
    SmemMain& S = *reinterpret_cast<SmemMain*>(smraw);
    const int tid = threadIdx.x, wid = tid >> 5, lane = tid & 31;
    const int bx = blockIdx.x;
    const int x0 = (bx & 3) << 5, y = (bx >> 2) & 127, b = bx >> 9;
    const int tokrow0 = (b*128 + y)*128 + x0;

    // ---- stage concatenated weight [Ad | Ar], biases, center terms ----
    for (int i = tid; i < 8192; i += 576) {
        int r = i >> 6, c = i & 63;
        unsigned int* Wu = reinterpret_cast<unsigned int*>(S.Wcat);
        Wu[r*(WS/2) + c]      = reinterpret_cast<const unsigned int*>(g_Ad)[i];
        Wu[r*(WS/2) + 64 + c] = reinterpret_cast<const unsigned int*>(g_Ar)[i];
    }
    for (int i = tid; i < NB*HID; i += 576) {
        int n = i >> 7, c = i & 127;
        S.relbd[n*132+c] = g_relbd[i]; S.relbr[n*132+c] = g_relbr[i];
    }
    for (int i = tid; i < TPB*128; i += 576) {
        int t = i >> 7, c = i & 127;
        S.Cds[t*132+c] = g_cd[(size_t)tokrow0*HID + i];
        S.Crs[t*132+c] = g_cr[(size_t)tokrow0*HID + i];
    }
    if (tid < 128) S.w2d[tid] = dW2[tid];
    else if (tid < 256) S.w2r[tid-128] = rW2[tid-128];

    // ---- gather scrambled neighborhood: Vs[t*9+n][c2] = norm[y+si-1, x+sj-1, c],
    //      where c*9+s = n*128+c2 (torch reshape semantics) ----
    for (int uidx = tid; uidx < TPB*144; uidx += 576) {
        int t = uidx / 144, rem = uidx - t*144;
        int s = rem >> 4, c0 = (rem & 15) << 3;
        int si = s / 3, sj = s - si*3;
        int yy = y + si - 1, xx = x0 + t + sj - 1;
        union { uint4 v; unsigned short h[8]; } pkt;
        if (yy >= 0 && yy < 128 && xx >= 0 && xx < 128) {
            pkt.v = *reinterpret_cast<const uint4*>(
                g_normbf + ((size_t)((b*128+yy)*128+xx))*CC + c0);
        } else {
            pkt.v = make_uint4(0,0,0,0);
        }
        unsigned short* vsrow = reinterpret_cast<unsigned short*>(S.Vs);
        #pragma unroll
        for (int k = 0; k < 8; k++) {
            int p = (c0 + k)*9 + s;
            vsrow[(t*9 + (p >> 7))*136 + (p & 127)] = pkt.h[k];
        }
    }
    __syncthreads();

    // ---- big GEMM: warp = (row-pair rp 0..8, half d/r). 32 rows x 128 cols per warp.
    //      fa preloaded (16 frags), fb double-buffered, shared across both bands.
    //      Epilogue directly from accumulator fragments (sm_80 mapping). ----
    {
        const int rp = wid >> 1, half = wid & 1;
        const int row0w = rp * 32;

        wmma::fragment<wmma::matrix_a,16,16,16,bf16,wmma::row_major> fa[2][8];
        #pragma unroll
        for (int bd = 0; bd < 2; bd++)
            #pragma unroll
            for (int kt = 0; kt < 8; kt++)
                wmma::load_matrix_sync(fa[bd][kt], S.Vs + (row0w + bd*16)*136 + kt*16, 136);

        const int g4 = lane >> 2, t4 = lane & 3;
        const int c0l = t4*2;
        int rw[4], tw[4], nw[4];
        #pragma unroll
        for (int i = 0; i < 4; i++) {
            rw[i] = row0w + (i>>1)*16 + (i&1)*8 + g4;   // i = bd*2 + hi
            tw[i] = rw[i] / 9; nw[i] = rw[i] - tw[i]*9;
        }
        const float* Cs = half ? S.Crs : S.Cds;
        const float* Rb = half ? S.relbr : S.relbd;
        const float* w2 = half ? S.w2r : S.w2d;
        float psum[4] = {0.f, 0.f, 0.f, 0.f};

        wmma::fragment<wmma::matrix_b,16,16,16,bf16,wmma::row_major> fbuf[2];
        wmma::fragment<wmma::accumulator,16,16,16,float> accA, accB;
        for (int ct = 0; ct < 8; ct++) {
            wmma::fill_fragment(accA, 0.0f);
            wmma::fill_fragment(accB, 0.0f);
            wmma::load_matrix_sync(fbuf[0], S.Wcat + half*128 + ct*16, WS);
            #pragma unroll
            for (int kt = 0; kt < 8; kt++) {
                if (kt < 7)
                    wmma::load_matrix_sync(fbuf[(kt+1)&1], S.Wcat + (kt+1)*16*WS + half*128 + ct*16, WS);
                wmma::mma_sync(accA, fa[0][kt], fbuf[kt&1], accA);
                wmma::mma_sync(accB, fa[1][kt], fbuf[kt&1], accB);
            }
            // element e: row = g4 + (e&2 ? 8:0); col = ct*16 + 2*(lane&3) + (e&1) + (e&4 ? 8:0)
            #pragma unroll
            for (int bd = 0; bd < 2; bd++) {
                const float* ax = bd ? accB.x : accA.x;
                #pragma unroll
                for (int ee = 0; ee < 8; ee += 2) {
                    const int colc = ct*16 + c0l + ((ee & 4) << 1);
                    const int idx = bd*2 + ((ee & 2) >> 1);
                    float2 cv = *reinterpret_cast<const float2*>(&Cs[tw[idx]*132 + colc]);
                    float2 rv = *reinterpret_cast<const float2*>(&Rb[nw[idx]*132 + colc]);
                    float2 wv = *reinterpret_cast<const float2*>(&w2[colc]);
                    float h0 = ax[ee]   + cv.x + rv.x;
                    float h1 = ax[ee+1] + cv.y + rv.y;
                    psum[idx] += gelu_fast(h0)*wv.x + gelu_fast(h1)*wv.y;
                }
            }
        }
        #pragma unroll
        for (int i = 0; i < 4; i++) {
            #pragma unroll
            for (int o = 1; o <= 2; o <<= 1)
                psum[i] += __shfl_xor_sync(0xffffffffu, psum[i], o);
        }
        if (t4 == 0) {
            float b2v = half ? rb2[0] : db2[0];
            float* dst = half ? S.resist : S.drive;
            #pragma unroll
            for (int i = 0; i < 4; i++) dst[rw[i]] = psum[i] + b2v;
        }
    }
    __syncthreads();

    // ---- gate ----
    if (tid < MROW) {
        float gamma = pg[0], lam = pl[0], bias = pb[0];
        float rres = S.resist[tid];
        float sp = (rres > 20.f) ? rres : log1pf(expf(rres));
        float e = gamma * S.drive[tid] / (lam * sp + 1e-6f) + bias;
        e = fminf(fmaxf(e, -3.0f), 3.0f);
        S.gate[tid] = 1.0f / (1.0f + expf(-e));
    }
    __syncthreads();

    // ---- gated neighbor sum -> mv (raw, bf16), gsum/invm folded in ----
    for (int uidx = tid; uidx < TPB*32; uidx += 576) {
        int t2 = uidx >> 5, cq = (uidx & 31) << 2;
        float gts[NB]; float gsm = 0.f;
        #pragma unroll
        for (int n2 = 0; n2 < 9; n2++) { gts[n2] = S.gate[t2*9+n2]; gsm += gts[n2]; }
        float a0=0.f, a1=0.f, a2=0.f, a3=0.f;
        #pragma unroll
        for (int n2 = 0; n2 < 9; n2++) {
            uint2 pk = *reinterpret_cast<const uint2*>(&S.Vs[(t2*9+n2)*136 + cq]);
            float2 v01 = __bfloat1622float2(*reinterpret_cast<__nv_bfloat162*>(&pk.x));
            float2 v23 = __bfloat1622float2(*reinterpret_cast<__nv_bfloat162*>(&pk.y));
            a0 += gts[n2]*v01.x; a1 += gts[n2]*v01.y;
            a2 += gts[n2]*v23.x; a3 += gts[n2]*v23.y;
        }
        uint2 ok;
        __nv_bfloat162 o01 = __floats2bfloat162_rn(a0, a1);
        __nv_bfloat162 o23 = __floats2bfloat162_rn(a2, a3);
        ok.x = *reinterpret_cast<unsigned int*>(&o01);
        ok.y = *reinterpret_cast<unsigned int*>(&o23);
        *reinterpret_cast<uint2*>(&S.mv[t2*136 + cq]) = ok;
        if (cq == 0) {
            S.gsum[t2] = gsm;
            S.invm[t2] = 1.0f / fmaxf(gsm, 1e-6f);
        }
    }
    __syncthreads();   // Vs now dead; alias its space

    bf16*  msg = reinterpret_cast<bf16*>(S.Vs);                     // TPBx136 bf16
    float* Us  = reinterpret_cast<float*>(reinterpret_cast<char*>(S.Vs) + 16384); // TPBx132 f32

    // ---- mv @ vW -> msg (bf16 direct fragment store) ----
    if (wid < 16) {
        int rt = wid >> 3, ctl = wid & 7;
        wmma::fragment<wmma::matrix_a,16,16,16,bf16,wmma::row_major> fa;
        wmma::fragment<wmma::matrix_b,16,16,16,bf16,wmma::row_major> fb;
        wmma::fragment<wmma::accumulator,16,16,16,float> acc;
        wmma::fill_fragment(acc, 0.0f);
        for (int kt = 0; kt < 8; kt++) {
            wmma::load_matrix_sync(fa, S.mv + rt*16*136 + kt*16, 136);
            wmma::load_matrix_sync(fb, g_vWb + kt*16*128 + ctl*16, 128);
            wmma::mma_sync(acc, fa, fb, acc);
        }
        const int g4 = lane >> 2, t4 = lane & 3;
        #pragma unroll
        for (int ee = 0; ee < 8; ee += 2) {
            int rloc = g4 + ((ee & 2) ? 8 : 0);
            int cloc = 2*t4 + ((ee & 4) ? 8 : 0);
            __nv_bfloat162 pr = __floats2bfloat162_rn(acc.x[ee], acc.x[ee+1]);
            *reinterpret_cast<__nv_bfloat162*>(
                &msg[(rt*16 + rloc)*136 + ctl*16 + cloc]) = pr;
        }
    }
    __syncthreads();
    // ---- msg @ oW -> Us (raw) ----
    if (wid < 16) {
        int rt = wid >> 3, ctl = wid & 7;
        wmma::fragment<wmma::matrix_a,16,16,16,bf16,wmma::row_major> fa;
        wmma::fragment<wmma::matrix_b,16,16,16,bf16,wmma::row_major> fb;
        wmma::fragment<wmma::accumulator,16,16,16,float> acc;
        wmma::fill_fragment(acc, 0.0f);
        for (int kt = 0; kt < 8; kt++) {
            wmma::load_matrix_sync(fa, msg + rt*16*136 + kt*16, 136);
            wmma::load_matrix_sync(fb, g_oWb + kt*16*128 + ctl*16, 128);
            wmma::mma_sync(acc, fa, fb, acc);
        }
        wmma::store_matrix_sync(Us + rt*16*132 + ctl*16, acc, 132, wmma::mem_row_major);
    }
    __syncthreads();
    // ---- LN2(tokens + invm*Us + invm*gsum*vbo + ob) ----
    for (int r = wid; r < TPB; r += 18) {
        size_t grow = (size_t)(tokrow0 + r) * CC;
        float im = S.invm[r], gs = S.gsum[r] * im;
        float4 tv = reinterpret_cast<const float4*>(tokens + grow)[lane];
        float4 uv = *reinterpret_cast<const float4*>(&Us[r*132 + 4*lane]);
        float4 ov = reinterpret_cast<const float4*>(ob)[lane];
        float4 bv = reinterpret_cast<const float4*>(g_vbo)[lane];
        float v0 = tv.x + uv.x*im + gs*bv.x + ov.x;
        float v1 = tv.y + uv.y*im + gs*bv.y + ov.y;
        float v2 = tv.z + uv.z*im + gs*bv.z + ov.z;
        float v3 = tv.w + uv.w*im + gs*bv.w + ov.w;
        float s = v0+v1+v2+v3;
        #pragma unroll
        for (int o = 16; o; o >>= 1) s += __shfl_xor_sync(0xffffffffu, s, o);
        float mean = s * (1.0f/128.0f);
        float d0=v0-mean, d1=v1-mean, d2=v2-mean, d3=v3-mean;
        float q = d0*d0+d1*d1+d2*d2+d3*d3;
        #pragma unroll
        for (int o = 16; o; o >>= 1) q += __shfl_xor_sync(0xffffffffu, q, o);
        float rstd = rsqrtf(q * (1.0f/128.0f) + 1e-5f);
        float4 gg = reinterpret_cast<const float4*>(ln2g)[lane];
        float4 bb = reinterpret_cast<const float4*>(ln2b)[lane];
        float4 o4;
        o4.x = d0*rstd*gg.x+bb.x; o4.y = d1*rstd*gg.y+bb.y;
        o4.z = d2*rstd*gg.z+bb.z; o4.w = d3*rstd*gg.w+bb.w;
        reinterpret_cast<float4*>(out + grow)[lane] = o4;
    }
}

// ================= launch =================
extern "C" void kernel_launch(void* const* d_in, const int* in_sizes, int n_in,
                              void* d_out, int out_size)
{
    const float* tokens = (const float*)d_in[0];
    const float* ln1g   = (const float*)d_in[1];
    const float* ln1b   = (const float*)d_in[2];
    const float* ln2g   = (const float*)d_in[3];
    const float* ln2b   = (const float*)d_in[4];
    const float* relp   = (const float*)d_in[5];
    const float* dW1    = (const float*)d_in[6];
    const float* db1    = (const float*)d_in[7];
    const float* dW2    = (const float*)d_in[8];
    const float* db2    = (const float*)d_in[9];
    const float* rW1    = (const float*)d_in[10];
    const float* rb1    = (const float*)d_in[11];
    const float* rW2    = (const float*)d_in[12];
    const float* rb2    = (const float*)d_in[13];
    const float* vW     = (const float*)d_in[14];
    const float* vb     = (const float*)d_in[15];
    const float* oW     = (const float*)d_in[16];
    const float* ob     = (const float*)d_in[17];
    const float* pg     = (const float*)d_in[18];
    const float* pl     = (const float*)d_in[19];
    const float* pb     = (const float*)d_in[20];
    float* out = (float*)d_out;

    static_assert(sizeof(SmemMain) <= 227000, "smem too big");
    cudaFuncSetAttribute(k_center, cudaFuncAttributeMaxDynamicSharedMemorySize, CSMEM);
    cudaFuncSetAttribute(k_main, cudaFuncAttributeMaxDynamicSharedMemorySize, (int)sizeof(SmemMain));

    k_prep<<<64, 256>>>(dW1, rW1, vW, oW, relp, db1, rb1, vb);
    k_ln1<<<4096, 256>>>(tokens, ln1g, ln1b);
    dim3 cgrid(256, 2);
    k_center<<<cgrid, 256, CSMEM>>>();
    k_main<<<1024, 576, sizeof(SmemMain)>>>(tokens, ln2g, ln2b, dW2, db2, rW2, rb2,
                                            ob, pg, pl, pb, out);
}

// round 14
// speedup vs baseline: 1.0961x; 1.0961x over previous
#include <cuda_runtime.h>
#include <cuda_bf16.h>
#include <mma.h>

using namespace nvcuda;
typedef __nv_bfloat16 bf16;

#define CC   128
#define NB   9
#define RPD  8
#define HID  128
#define NTOK 32768
#define TPB  32          // tokens per main block
#define MROW (TPB*NB)    // 288 edge rows
#define WS   272         // Wcat bf16 stride (cols 0-127 drive, 128-255 resist)

// ---- device scratch (no runtime allocation) ----
__device__ bf16  g_normbf[NTOK*CC];
__device__ float g_cd[NTOK*HID];
__device__ float g_cr[NTOK*HID];
__device__ bf16  g_Ad[CC*HID], g_Ar[CC*HID];   // Wn - Wd
__device__ bf16  g_Bd[CC*HID], g_Br[CC*HID];   // Wc + Wd
__device__ bf16  g_vWb[CC*CC], g_oWb[CC*CC];
__device__ float g_relbd[NB*HID], g_relbr[NB*HID];
__device__ float g_vbo[CC];                     // vb @ oW

__device__ __forceinline__ float gelu_fast(float x) {
    float u = 0.7978845608f * x * (1.0f + 0.044715f * x * x);
    float t;
    asm("tanh.approx.f32 %0, %1;" : "=f"(t) : "f"(u));
    return 0.5f * x * (1.0f + t);
}

// ================= kernel 0: fold weights, rel-bias tables =================
__global__ void k_prep(const float* __restrict__ dW1, const float* __restrict__ rW1,
                       const float* __restrict__ vW,  const float* __restrict__ oW,
                       const float* __restrict__ rel_pos,
                       const float* __restrict__ db1, const float* __restrict__ rb1)
{
    int i = blockIdx.x * blockDim.x + threadIdx.x;
    if (i >= CC*HID) return;
    int c = i >> 7, h = i & 127;
    g_Ad[i] = __float2bfloat16(dW1[(CC+c)*HID+h]   - dW1[(2*CC+c)*HID+h]);
    g_Bd[i] = __float2bfloat16(dW1[c*HID+h]        + dW1[(2*CC+c)*HID+h]);
    g_Ar[i] = __float2bfloat16(rW1[(CC+c)*HID+h]   - rW1[(2*CC+c)*HID+h]);
    g_Br[i] = __float2bfloat16(rW1[c*HID+h]        + rW1[(2*CC+c)*HID+h]);
    g_vWb[i] = __float2bfloat16(vW[i]);
    g_oWb[i] = __float2bfloat16(oW[i]);
    if (i < NB*HID) {
        int n = i >> 7;
        float sd = db1[h], sr = rb1[h];
        #pragma unroll
        for (int r = 0; r < RPD; r++) {
            float rp = rel_pos[n*RPD + r];
            sd += rp * dW1[(3*CC+r)*HID+h];
            sr += rp * rW1[(3*CC+r)*HID+h];
        }
        g_relbd[i] = sd; g_relbr[i] = sr;
    }
}

// ================= kernel 0b: vbo = vb @ oW (warp per output) =================
__global__ void k_vbo(const float* __restrict__ vb, const float* __restrict__ oW)
{
    int wid = threadIdx.x >> 5, lane = threadIdx.x & 31;
    int o = blockIdx.x * 4 + wid;           // 32 blocks x 4 warps = 128 outputs
    float s = 0.f;
    #pragma unroll
    for (int k = 0; k < 4; k++) {
        int c2 = k*32 + lane;
        s += vb[c2] * oW[c2*CC + o];
    }
    #pragma unroll
    for (int off = 16; off; off >>= 1) s += __shfl_xor_sync(0xffffffffu, s, off);
    if (lane == 0) g_vbo[o] = s;
}

// ================= kernel 1: LayerNorm1 -> bf16 =================
__global__ void k_ln1(const float* __restrict__ tokens,
                      const float* __restrict__ g, const float* __restrict__ b)
{
    int wid = threadIdx.x >> 5, lane = threadIdx.x & 31;
    int row = blockIdx.x * 8 + wid;
    float4 v = reinterpret_cast<const float4*>(tokens + (size_t)row*CC)[lane];
    float s = v.x + v.y + v.z + v.w;
    #pragma unroll
    for (int o = 16; o; o >>= 1) s += __shfl_xor_sync(0xffffffffu, s, o);
    float mean = s * (1.0f/128.0f);
    float d0=v.x-mean, d1=v.y-mean, d2=v.z-mean, d3=v.w-mean;
    float q = d0*d0+d1*d1+d2*d2+d3*d3;
    #pragma unroll
    for (int o = 16; o; o >>= 1) q += __shfl_xor_sync(0xffffffffu, q, o);
    float rstd = rsqrtf(q * (1.0f/128.0f) + 1e-5f);
    float4 gg = reinterpret_cast<const float4*>(g)[lane];
    float4 bb = reinterpret_cast<const float4*>(b)[lane];
    __nv_bfloat162 p0 = __floats2bfloat162_rn(d0*rstd*gg.x+bb.x, d1*rstd*gg.y+bb.y);
    __nv_bfloat162 p1 = __floats2bfloat162_rn(d2*rstd*gg.z+bb.z, d3*rstd*gg.w+bb.w);
    uint2 pk; pk.x = *reinterpret_cast<unsigned int*>(&p0); pk.y = *reinterpret_cast<unsigned int*>(&p1);
    reinterpret_cast<uint2*>(g_normbf + (size_t)row*CC)[lane] = pk;
}

// ================= kernel 2: center GEMMs (split drive/resist by blockIdx.y) =========
#define CSMEM (2*128*136*2)
__global__ void __launch_bounds__(256) k_center()
{
    extern __shared__ char sm[];
    bf16* Xs = reinterpret_cast<bf16*>(sm);
    bf16* Ws = Xs + 128*136;
    int tid = threadIdx.x, wid = tid >> 5;
    int row0 = blockIdx.x * 128;
    int which = blockIdx.y;
    const bf16* Wg = which ? g_Br : g_Bd;
    float* outg = which ? g_cr : g_cd;
    for (int i = tid; i < 8192; i += 256) {
        int r = i >> 6, c = i & 63;
        reinterpret_cast<unsigned int*>(Ws)[r*68+c] = reinterpret_cast<const unsigned int*>(Wg)[i];
        reinterpret_cast<unsigned int*>(Xs)[r*68+c] =
            reinterpret_cast<const unsigned int*>(g_normbf + (size_t)row0*CC)[i];
    }
    __syncthreads();
    wmma::fragment<wmma::matrix_a,16,16,16,bf16,wmma::row_major> fa;
    wmma::fragment<wmma::matrix_b,16,16,16,bf16,wmma::row_major> fb;
    wmma::fragment<wmma::accumulator,16,16,16,float> acc[8];
    #pragma unroll
    for (int ct = 0; ct < 8; ct++) wmma::fill_fragment(acc[ct], 0.0f);
    for (int kt = 0; kt < 8; kt++) {
        wmma::load_matrix_sync(fa, Xs + wid*16*136 + kt*16, 136);
        #pragma unroll
        for (int ct = 0; ct < 8; ct++) {
            wmma::load_matrix_sync(fb, Ws + kt*16*136 + ct*16, 136);
            wmma::mma_sync(acc[ct], fa, fb, acc[ct]);
        }
    }
    #pragma unroll
    for (int ct = 0; ct < 8; ct++)
        wmma::store_matrix_sync(outg + (size_t)(row0+wid*16)*HID + ct*16, acc[ct], HID, wmma::mem_row_major);
}

// ================= main fused kernel =================
// bf16x2 tables stored as uint arrays, 68 uints (=136 bf16) per row
struct SmemMain {
    bf16 Wcat[128*WS];            // 69.6 KB
    bf16 Vs[MROW*136];            // 78.3 KB (later aliased by msg/Us)
    bf16 mv[TPB*136];             // 8.7 KB
    unsigned int Cdu[TPB*68], Cru[TPB*68];    // 17.4 KB (bf16x2)
    unsigned int Rdu[NB*68],  Rru[NB*68];     // 4.9 KB
    unsigned int w2du[64], w2ru[64];          // 0.5 KB
    float drive[MROW], resist[MROW], gate[MROW];
    float gsum[TPB], invm[TPB];
};

__global__ void __launch_bounds__(576, 1) k_main(
    const float* __restrict__ tokens,
    const float* __restrict__ ln2g, const float* __restrict__ ln2b,
    const float* __restrict__ dW2,  const float* __restrict__ db2,
    const float* __restrict__ rW2,  const float* __restrict__ rb2,
    const float* __restrict__ ob,
    const float* __restrict__ pg, const float* __restrict__ pl, const float* __restrict__ pb,
    float* __restrict__ out)
{
    extern __shared__ char smraw[];
    SmemMain& S = *reinterpret_cast<SmemMain*>(smraw);
    const int tid = threadIdx.x, wid = tid >> 5, lane = tid & 31;
    const int bx = blockIdx.x;
    const int x0 = (bx & 3) << 5, y = (bx >> 2) & 127, b = bx >> 9;
    const int tokrow0 = (b*128 + y)*128 + x0;

    // ---- stage concatenated weight [Ad | Ar] ----
    for (int i = tid; i < 8192; i += 576) {
        int r = i >> 6, c = i & 63;
        unsigned int* Wu = reinterpret_cast<unsigned int*>(S.Wcat);
        Wu[r*(WS/2) + c]      = reinterpret_cast<const unsigned int*>(g_Ad)[i];
        Wu[r*(WS/2) + 64 + c] = reinterpret_cast<const unsigned int*>(g_Ar)[i];
    }
    // ---- stage tables as bf16x2 ----
    for (int i = tid; i < NB*64; i += 576) {
        int n = i >> 6, cp = (i & 63) << 1;
        float2 fd = *reinterpret_cast<const float2*>(&g_relbd[n*HID + cp]);
        float2 fr = *reinterpret_cast<const float2*>(&g_relbr[n*HID + cp]);
        __nv_bfloat162 bd = __floats2bfloat162_rn(fd.x, fd.y);
        __nv_bfloat162 br = __floats2bfloat162_rn(fr.x, fr.y);
        S.Rdu[n*68 + (cp>>1)] = *reinterpret_cast<unsigned int*>(&bd);
        S.Rru[n*68 + (cp>>1)] = *reinterpret_cast<unsigned int*>(&br);
    }
    for (int i = tid; i < TPB*64; i += 576) {
        int t = i >> 6, cp = (i & 63) << 1;
        float2 fd = *reinterpret_cast<const float2*>(&g_cd[(size_t)(tokrow0+t)*HID + cp]);
        float2 fr = *reinterpret_cast<const float2*>(&g_cr[(size_t)(tokrow0+t)*HID + cp]);
        __nv_bfloat162 bd = __floats2bfloat162_rn(fd.x, fd.y);
        __nv_bfloat162 br = __floats2bfloat162_rn(fr.x, fr.y);
        S.Cdu[t*68 + (cp>>1)] = *reinterpret_cast<unsigned int*>(&bd);
        S.Cru[t*68 + (cp>>1)] = *reinterpret_cast<unsigned int*>(&br);
    }
    if (tid < 64) {
        float2 fd = *reinterpret_cast<const float2*>(&dW2[tid*2]);
        __nv_bfloat162 bd = __floats2bfloat162_rn(fd.x, fd.y);
        S.w2du[tid] = *reinterpret_cast<unsigned int*>(&bd);
    } else if (tid < 128) {
        int j = tid - 64;
        float2 fr = *reinterpret_cast<const float2*>(&rW2[j*2]);
        __nv_bfloat162 br = __floats2bfloat162_rn(fr.x, fr.y);
        S.w2ru[j] = *reinterpret_cast<unsigned int*>(&br);
    }

    // ---- gather scrambled neighborhood: Vs[t*9+n][c2] = norm[y+si-1, x+sj-1, c],
    //      where c*9+s = n*128+c2 (torch reshape semantics) ----
    for (int uidx = tid; uidx < TPB*144; uidx += 576) {
        int t = uidx / 144, rem = uidx - t*144;
        int s = rem >> 4, c0 = (rem & 15) << 3;
        int si = s / 3, sj = s - si*3;
        int yy = y + si - 1, xx = x0 + t + sj - 1;
        union { uint4 v; unsigned short h[8]; } pkt;
        if (yy >= 0 && yy < 128 && xx >= 0 && xx < 128) {
            pkt.v = *reinterpret_cast<const uint4*>(
                g_normbf + ((size_t)((b*128+yy)*128+xx))*CC + c0);
        } else {
            pkt.v = make_uint4(0,0,0,0);
        }
        unsigned short* vsrow = reinterpret_cast<unsigned short*>(S.Vs);
        #pragma unroll
        for (int k = 0; k < 8; k++) {
            int p = (c0 + k)*9 + s;
            vsrow[(t*9 + (p >> 7))*136 + (p & 127)] = pkt.h[k];
        }
    }
    __syncthreads();

    // ---- big GEMM: warp = (row-pair rp 0..8, half d/r). 32 rows x 128 cols per warp.
    //      fa preloaded (16 frags), fb double-buffered, shared across both bands.
    //      Epilogue from accumulator fragments, bf16x2 table loads. ----
    {
        const int rp = wid >> 1, half = wid & 1;
        const int row0w = rp * 32;

        wmma::fragment<wmma::matrix_a,16,16,16,bf16,wmma::row_major> fa[2][8];
        #pragma unroll
        for (int bd = 0; bd < 2; bd++)
            #pragma unroll
            for (int kt = 0; kt < 8; kt++)
                wmma::load_matrix_sync(fa[bd][kt], S.Vs + (row0w + bd*16)*136 + kt*16, 136);

        const int g4 = lane >> 2, t4 = lane & 3;
        const int c0l = t4*2;
        int rw[4], tw[4], nw[4];
        #pragma unroll
        for (int i = 0; i < 4; i++) {
            rw[i] = row0w + (i>>1)*16 + (i&1)*8 + g4;   // i = bd*2 + hi
            tw[i] = rw[i] / 9; nw[i] = rw[i] - tw[i]*9;
        }
        const unsigned int* Cu = half ? S.Cru : S.Cdu;
        const unsigned int* Ru = half ? S.Rru : S.Rdu;
        const unsigned int* Wu2 = half ? S.w2ru : S.w2du;
        float psum[4] = {0.f, 0.f, 0.f, 0.f};

        wmma::fragment<wmma::matrix_b,16,16,16,bf16,wmma::row_major> fbuf[2];
        wmma::fragment<wmma::accumulator,16,16,16,float> accA, accB;
        for (int ct = 0; ct < 8; ct++) {
            wmma::fill_fragment(accA, 0.0f);
            wmma::fill_fragment(accB, 0.0f);
            wmma::load_matrix_sync(fbuf[0], S.Wcat + half*128 + ct*16, WS);
            #pragma unroll
            for (int kt = 0; kt < 8; kt++) {
                if (kt < 7)
                    wmma::load_matrix_sync(fbuf[(kt+1)&1], S.Wcat + (kt+1)*16*WS + half*128 + ct*16, WS);
                wmma::mma_sync(accA, fa[0][kt], fbuf[kt&1], accA);
                wmma::mma_sync(accB, fa[1][kt], fbuf[kt&1], accB);
            }
            // cols: cA = ct*16 + c0l, cB = cA + 8 (uint index = col/2)
            const int uA = (ct*16 + c0l) >> 1, uB = uA + 4;
            unsigned int wau = Wu2[uA], wbu = Wu2[uB];
            float2 wvA = __bfloat1622float2(*reinterpret_cast<__nv_bfloat162*>(&wau));
            float2 wvB = __bfloat1622float2(*reinterpret_cast<__nv_bfloat162*>(&wbu));
            #pragma unroll
            for (int idx = 0; idx < 4; idx++) {
                const float* ax = (idx >= 2) ? accB.x : accA.x;
                const int eb = (idx & 1) ? 2 : 0;      // element base for cA
                unsigned int cua = Cu[tw[idx]*68 + uA], cub = Cu[tw[idx]*68 + uB];
                unsigned int rua = Ru[nw[idx]*68 + uA], rub = Ru[nw[idx]*68 + uB];
                float2 cvA = __bfloat1622float2(*reinterpret_cast<__nv_bfloat162*>(&cua));
                float2 cvB = __bfloat1622float2(*reinterpret_cast<__nv_bfloat162*>(&cub));
                float2 rvA = __bfloat1622float2(*reinterpret_cast<__nv_bfloat162*>(&rua));
                float2 rvB = __bfloat1622float2(*reinterpret_cast<__nv_bfloat162*>(&rub));
                psum[idx] += gelu_fast(ax[eb]   + cvA.x + rvA.x) * wvA.x
                           + gelu_fast(ax[eb+1] + cvA.y + rvA.y) * wvA.y
                           + gelu_fast(ax[eb+4] + cvB.x + rvB.x) * wvB.x
                           + gelu_fast(ax[eb+5] + cvB.y + rvB.y) * wvB.y;
            }
        }
        #pragma unroll
        for (int i = 0; i < 4; i++) {
            #pragma unroll
            for (int o = 1; o <= 2; o <<= 1)
                psum[i] += __shfl_xor_sync(0xffffffffu, psum[i], o);
        }
        if (t4 == 0) {
            float b2v = half ? rb2[0] : db2[0];
            float* dst = half ? S.resist : S.drive;
            #pragma unroll
            for (int i = 0; i < 4; i++) dst[rw[i]] = psum[i] + b2v;
        }
    }
    __syncthreads();

    // ---- gate ----
    if (tid < MROW) {
        float gamma = pg[0], lam = pl[0], bias = pb[0];
        float rres = S.resist[tid];
        float sp = (rres > 20.f) ? rres : log1pf(expf(rres));
        float e = gamma * S.drive[tid] / (lam * sp + 1e-6f) + bias;
        e = fminf(fmaxf(e, -3.0f), 3.0f);
        S.gate[tid] = 1.0f / (1.0f + expf(-e));
    }
    __syncthreads();

    // ---- gated neighbor sum -> mv (raw, bf16), gsum/invm folded in ----
    for (int uidx = tid; uidx < TPB*32; uidx += 576) {
        int t2 = uidx >> 5, cq = (uidx & 31) << 2;
        float gts[NB]; float gsm = 0.f;
        #pragma unroll
        for (int n2 = 0; n2 < 9; n2++) { gts[n2] = S.gate[t2*9+n2]; gsm += gts[n2]; }
        float a0=0.f, a1=0.f, a2=0.f, a3=0.f;
        #pragma unroll
        for (int n2 = 0; n2 < 9; n2++) {
            uint2 pk = *reinterpret_cast<const uint2*>(&S.Vs[(t2*9+n2)*136 + cq]);
            float2 v01 = __bfloat1622float2(*reinterpret_cast<__nv_bfloat162*>(&pk.x));
            float2 v23 = __bfloat1622float2(*reinterpret_cast<__nv_bfloat162*>(&pk.y));
            a0 += gts[n2]*v01.x; a1 += gts[n2]*v01.y;
            a2 += gts[n2]*v23.x; a3 += gts[n2]*v23.y;
        }
        uint2 ok;
        __nv_bfloat162 o01 = __floats2bfloat162_rn(a0, a1);
        __nv_bfloat162 o23 = __floats2bfloat162_rn(a2, a3);
        ok.x = *reinterpret_cast<unsigned int*>(&o01);
        ok.y = *reinterpret_cast<unsigned int*>(&o23);
        *reinterpret_cast<uint2*>(&S.mv[t2*136 + cq]) = ok;
        if (cq == 0) {
            S.gsum[t2] = gsm;
            S.invm[t2] = 1.0f / fmaxf(gsm, 1e-6f);
        }
    }
    __syncthreads();   // Vs now dead; alias its space

    bf16*  msg = reinterpret_cast<bf16*>(S.Vs);                     // TPBx136 bf16
    float* Us  = reinterpret_cast<float*>(reinterpret_cast<char*>(S.Vs) + 16384); // TPBx132 f32

    // ---- mv @ vW -> msg (bf16 direct fragment store) ----
    if (wid < 16) {
        int rt = wid >> 3, ctl = wid & 7;
        wmma::fragment<wmma::matrix_a,16,16,16,bf16,wmma::row_major> fa;
        wmma::fragment<wmma::matrix_b,16,16,16,bf16,wmma::row_major> fb;
        wmma::fragment<wmma::accumulator,16,16,16,float> acc;
        wmma::fill_fragment(acc, 0.0f);
        for (int kt = 0; kt < 8; kt++) {
            wmma::load_matrix_sync(fa, S.mv + rt*16*136 + kt*16, 136);
            wmma::load_matrix_sync(fb, g_vWb + kt*16*128 + ctl*16, 128);
            wmma::mma_sync(acc, fa, fb, acc);
        }
        const int g4 = lane >> 2, t4 = lane & 3;
        #pragma unroll
        for (int ee = 0; ee < 8; ee += 2) {
            int rloc = g4 + ((ee & 2) ? 8 : 0);
            int cloc = 2*t4 + ((ee & 4) ? 8 : 0);
            __nv_bfloat162 pr = __floats2bfloat162_rn(acc.x[ee], acc.x[ee+1]);
            *reinterpret_cast<__nv_bfloat162*>(
                &msg[(rt*16 + rloc)*136 + ctl*16 + cloc]) = pr;
        }
    }
    __syncthreads();
    // ---- msg @ oW -> Us (raw) ----
    if (wid < 16) {
        int rt = wid >> 3, ctl = wid & 7;
        wmma::fragment<wmma::matrix_a,16,16,16,bf16,wmma::row_major> fa;
        wmma::fragment<wmma::matrix_b,16,16,16,bf16,wmma::row_major> fb;
        wmma::fragment<wmma::accumulator,16,16,16,float> acc;
        wmma::fill_fragment(acc, 0.0f);
        for (int kt = 0; kt < 8; kt++) {
            wmma::load_matrix_sync(fa, msg + rt*16*136 + kt*16, 136);
            wmma::load_matrix_sync(fb, g_oWb + kt*16*128 + ctl*16, 128);
            wmma::mma_sync(acc, fa, fb, acc);
        }
        wmma::store_matrix_sync(Us + rt*16*132 + ctl*16, acc, 132, wmma::mem_row_major);
    }
    __syncthreads();
    // ---- LN2(tokens + invm*Us + invm*gsum*vbo + ob) ----
    for (int r = wid; r < TPB; r += 18) {
        size_t grow = (size_t)(tokrow0 + r) * CC;
        float im = S.invm[r], gs = S.gsum[r] * im;
        float4 tv = reinterpret_cast<const float4*>(tokens + grow)[lane];
        float4 uv = *reinterpret_cast<const float4*>(&Us[r*132 + 4*lane]);
        float4 ov = reinterpret_cast<const float4*>(ob)[lane];
        float4 bv = reinterpret_cast<const float4*>(g_vbo)[lane];
        float v0 = tv.x + uv.x*im + gs*bv.x + ov.x;
        float v1 = tv.y + uv.y*im + gs*bv.y + ov.y;
        float v2 = tv.z + uv.z*im + gs*bv.z + ov.z;
        float v3 = tv.w + uv.w*im + gs*bv.w + ov.w;
        float s = v0+v1+v2+v3;
        #pragma unroll
        for (int o = 16; o; o >>= 1) s += __shfl_xor_sync(0xffffffffu, s, o);
        float mean = s * (1.0f/128.0f);
        float d0=v0-mean, d1=v1-mean, d2=v2-mean, d3=v3-mean;
        float q = d0*d0+d1*d1+d2*d2+d3*d3;
        #pragma unroll
        for (int o = 16; o; o >>= 1) q += __shfl_xor_sync(0xffffffffu, q, o);
        float rstd = rsqrtf(q * (1.0f/128.0f) + 1e-5f);
        float4 gg = reinterpret_cast<const float4*>(ln2g)[lane];
        float4 bb = reinterpret_cast<const float4*>(ln2b)[lane];
        float4 o4;
        o4.x = d0*rstd*gg.x+bb.x; o4.y = d1*rstd*gg.y+bb.y;
        o4.z = d2*rstd*gg.z+bb.z; o4.w = d3*rstd*gg.w+bb.w;
        reinterpret_cast<float4*>(out + grow)[lane] = o4;
    }
}

// ================= launch =================
extern "C" void kernel_launch(void* const* d_in, const int* in_sizes, int n_in,
                              void* d_out, int out_size)
{
    const float* tokens = (const float*)d_in[0];
    const float* ln1g   = (const float*)d_in[1];
    const float* ln1b   = (const float*)d_in[2];
    const float* ln2g   = (const float*)d_in[3];
    const float* ln2b   = (const float*)d_in[4];
    const float* relp   = (const float*)d_in[5];
    const float* dW1    = (const float*)d_in[6];
    const float* db1    = (const float*)d_in[7];
    const float* dW2    = (const float*)d_in[8];
    const float* db2    = (const float*)d_in[9];
    const float* rW1    = (const float*)d_in[10];
    const float* rb1    = (const float*)d_in[11];
    const float* rW2    = (const float*)d_in[12];
    const float* rb2    = (const float*)d_in[13];
    const float* vW     = (const float*)d_in[14];
    const float* vb     = (const float*)d_in[15];
    const float* oW     = (const float*)d_in[16];
    const float* ob     = (const float*)d_in[17];
    const float* pg     = (const float*)d_in[18];
    const float* pl     = (const float*)d_in[19];
    const float* pb     = (const float*)d_in[20];
    float* out = (float*)d_out;

    static_assert(sizeof(SmemMain) <= 200000, "smem too big");
    cudaFuncSetAttribute(k_center, cudaFuncAttributeMaxDynamicSharedMemorySize, CSMEM);
    cudaFuncSetAttribute(k_main, cudaFuncAttributeMaxDynamicSharedMemorySize, (int)sizeof(SmemMain));

    k_prep<<<64, 256>>>(dW1, rW1, vW, oW, relp, db1, rb1);
    k_vbo<<<32, 128>>>(vb, oW);
    k_ln1<<<4096, 256>>>(tokens, ln1g, ln1b);
    dim3 cgrid(256, 2);
    k_center<<<cgrid, 256, CSMEM>>>();
    k_main<<<1024, 576, sizeof(SmemMain)>>>(tokens, ln2g, ln2b, dW2, db2, rW2, rb2,
                                            ob, pg, pl, pb, out);
}

// round 16
// speedup vs baseline: 1.1057x; 1.0088x over previous
#include <cuda_runtime.h>
#include <cuda_bf16.h>
#include <mma.h>

using namespace nvcuda;
typedef __nv_bfloat16 bf16;

#define CC   128
#define NB   9
#define RPD  8
#define HID  128
#define NTOK 32768
#define TPB  32          // tokens per main block
#define MROW (TPB*NB)    // 288 edge rows
#define WS   272         // Wcat bf16 stride (cols 0-127 drive, 128-255 resist)

// ---- device scratch (no runtime allocation) ----
__device__ bf16  g_normbf[NTOK*CC];
__device__ unsigned int g_cdu[NTOK*64];        // center drive terms, bf16x2 packed
__device__ unsigned int g_cru[NTOK*64];        // center resist terms, bf16x2 packed
__device__ bf16  g_Ad[CC*HID], g_Ar[CC*HID];   // Wn - Wd
__device__ bf16  g_Bd[CC*HID], g_Br[CC*HID];   // Wc + Wd
__device__ bf16  g_vWb[CC*CC], g_oWb[CC*CC];
__device__ float g_relbd[NB*HID], g_relbr[NB*HID];
__device__ float g_vbo[CC];                     // vb @ oW

__device__ __forceinline__ float gelu_fast(float x) {
    float u = 0.7978845608f * x * (1.0f + 0.044715f * x * x);
    float t;
    asm("tanh.approx.f32 %0, %1;" : "=f"(t) : "f"(u));
    return 0.5f * x * (1.0f + t);
}

// ================= kernel 0: fold weights, rel-bias tables =================
__global__ void k_prep(const float* __restrict__ dW1, const float* __restrict__ rW1,
                       const float* __restrict__ vW,  const float* __restrict__ oW,
                       const float* __restrict__ rel_pos,
                       const float* __restrict__ db1, const float* __restrict__ rb1)
{
    int i = blockIdx.x * blockDim.x + threadIdx.x;
    if (i >= CC*HID) return;
    int c = i >> 7, h = i & 127;
    g_Ad[i] = __float2bfloat16(dW1[(CC+c)*HID+h]   - dW1[(2*CC+c)*HID+h]);
    g_Bd[i] = __float2bfloat16(dW1[c*HID+h]        + dW1[(2*CC+c)*HID+h]);
    g_Ar[i] = __float2bfloat16(rW1[(CC+c)*HID+h]   - rW1[(2*CC+c)*HID+h]);
    g_Br[i] = __float2bfloat16(rW1[c*HID+h]        + rW1[(2*CC+c)*HID+h]);
    g_vWb[i] = __float2bfloat16(vW[i]);
    g_oWb[i] = __float2bfloat16(oW[i]);
    if (i < NB*HID) {
        int n = i >> 7;
        float sd = db1[h], sr = rb1[h];
        #pragma unroll
        for (int r = 0; r < RPD; r++) {
            float rp = rel_pos[n*RPD + r];
            sd += rp * dW1[(3*CC+r)*HID+h];
            sr += rp * rW1[(3*CC+r)*HID+h];
        }
        g_relbd[i] = sd; g_relbr[i] = sr;
    }
}

// ================= kernel 0b: vbo = vb @ oW (warp per output) =================
__global__ void k_vbo(const float* __restrict__ vb, const float* __restrict__ oW)
{
    int wid = threadIdx.x >> 5, lane = threadIdx.x & 31;
    int o = blockIdx.x * 4 + wid;           // 32 blocks x 4 warps = 128 outputs
    float s = 0.f;
    #pragma unroll
    for (int k = 0; k < 4; k++) {
        int c2 = k*32 + lane;
        s += vb[c2] * oW[c2*CC + o];
    }
    #pragma unroll
    for (int off = 16; off; off >>= 1) s += __shfl_xor_sync(0xffffffffu, s, off);
    if (lane == 0) g_vbo[o] = s;
}

// ================= kernel 2: LN1 + center GEMMs (drive/resist by blockIdx.y) =========
#define CSMEM (2*128*136*2)
__global__ void __launch_bounds__(256) k_center(const float* __restrict__ tokens,
                                                const float* __restrict__ lg,
                                                const float* __restrict__ lb)
{
    extern __shared__ char sm[];
    bf16* Xs = reinterpret_cast<bf16*>(sm);
    bf16* Ws = Xs + 128*136;
    int tid = threadIdx.x, wid = tid >> 5, lane = tid & 31;
    int row0 = blockIdx.x * 128;
    int which = blockIdx.y;
    const bf16* Wg = which ? g_Br : g_Bd;
    unsigned int* outg = which ? g_cru : g_cdu;

    // stage weight tile
    for (int i = tid; i < 8192; i += 256) {
        int r = i >> 6, c = i & 63;
        reinterpret_cast<unsigned int*>(Ws)[r*68+c] = reinterpret_cast<const unsigned int*>(Wg)[i];
    }
    // LN1 for this block's 128 rows -> Xs (+ g_normbf once)
    float4 gg = reinterpret_cast<const float4*>(lg)[lane];
    float4 bb = reinterpret_cast<const float4*>(lb)[lane];
    for (int pass = 0; pass < 16; pass++) {
        int r = pass*8 + wid;
        float4 v = reinterpret_cast<const float4*>(tokens + (size_t)(row0+r)*CC)[lane];
        float s = v.x + v.y + v.z + v.w;
        #pragma unroll
        for (int o = 16; o; o >>= 1) s += __shfl_xor_sync(0xffffffffu, s, o);
        float mean = s * (1.0f/128.0f);
        float d0=v.x-mean, d1=v.y-mean, d2=v.z-mean, d3=v.w-mean;
        float q = d0*d0+d1*d1+d2*d2+d3*d3;
        #pragma unroll
        for (int o = 16; o; o >>= 1) q += __shfl_xor_sync(0xffffffffu, q, o);
        float rstd = rsqrtf(q * (1.0f/128.0f) + 1e-5f);
        __nv_bfloat162 p0 = __floats2bfloat162_rn(d0*rstd*gg.x+bb.x, d1*rstd*gg.y+bb.y);
        __nv_bfloat162 p1 = __floats2bfloat162_rn(d2*rstd*gg.z+bb.z, d3*rstd*gg.w+bb.w);
        uint2 pk;
        pk.x = *reinterpret_cast<unsigned int*>(&p0);
        pk.y = *reinterpret_cast<unsigned int*>(&p1);
        *reinterpret_cast<uint2*>(reinterpret_cast<unsigned int*>(Xs) + r*68 + 2*lane) = pk;
        if (which == 0)
            reinterpret_cast<uint2*>(g_normbf + (size_t)(row0+r)*CC)[lane] = pk;
    }
    __syncthreads();

    wmma::fragment<wmma::matrix_a,16,16,16,bf16,wmma::row_major> fa;
    wmma::fragment<wmma::matrix_b,16,16,16,bf16,wmma::row_major> fb;
    wmma::fragment<wmma::accumulator,16,16,16,float> acc[8];
    #pragma unroll
    for (int ct = 0; ct < 8; ct++) wmma::fill_fragment(acc[ct], 0.0f);
    for (int kt = 0; kt < 8; kt++) {
        wmma::load_matrix_sync(fa, Xs + wid*16*136 + kt*16, 136);
        #pragma unroll
        for (int ct = 0; ct < 8; ct++) {
            wmma::load_matrix_sync(fb, Ws + kt*16*136 + ct*16, 136);
            wmma::mma_sync(acc[ct], fa, fb, acc[ct]);
        }
    }
    // pack accumulators to bf16x2 directly (sm_80 fragment mapping)
    {
        const int g4 = lane >> 2, t4 = lane & 3;
        #pragma unroll
        for (int ct = 0; ct < 8; ct++) {
            #pragma unroll
            for (int e = 0; e < 8; e += 2) {
                int rowl = g4 + ((e & 2) ? 8 : 0);
                int j = ct*8 + t4 + ((e & 4) ? 4 : 0);
                __nv_bfloat162 pr = __floats2bfloat162_rn(acc[ct].x[e], acc[ct].x[e+1]);
                outg[(size_t)(row0 + wid*16 + rowl)*64 + j] = *reinterpret_cast<unsigned int*>(&pr);
            }
        }
    }
}

// ================= main fused kernel =================
// bf16x2 tables stored as uint arrays, 68 uints (=136 bf16) per row
struct SmemMain {
    bf16 Wcat[128*WS];            // 69.6 KB
    bf16 Vs[MROW*136];            // 78.3 KB (later aliased by msg/Us)
    bf16 mv[TPB*136];             // 8.7 KB
    unsigned int Cdu[TPB*68], Cru[TPB*68];    // 17.4 KB (bf16x2)
    unsigned int Rdu[NB*68],  Rru[NB*68];     // 4.9 KB
    unsigned int w2du[64], w2ru[64];          // 0.5 KB
    float drive[MROW], resist[MROW], gate[MROW];
    float gsum[TPB], invm[TPB];
};

__global__ void __launch_bounds__(576, 1) k_main(
    const float* __restrict__ tokens,
    const float* __restrict__ ln2g, const float* __restrict__ ln2b,
    const float* __restrict__ dW2,  const float* __restrict__ db2,
    const float* __restrict__ rW2,  const float* __restrict__ rb2,
    const float* __restrict__ ob,
    const float* __restrict__ pg, const float* __restrict__ pl, const float* __restrict__ pb,
    float* __restrict__ out)
{
    extern __shared__ char smraw[];
    SmemMain& S = *reinterpret_cast<SmemMain*>(smraw);
    const int tid = threadIdx.x, wid = tid >> 5, lane = tid & 31;
    const int bx = blockIdx.x;
    const int x0 = (bx & 3) << 5, y = (bx >> 2) & 127, b = bx >> 9;
    const int tokrow0 = (b*128 + y)*128 + x0;

    // ---- stage concatenated weight [Ad | Ar] ----
    for (int i = tid; i < 8192; i += 576) {
        int r = i >> 6, c = i & 63;
        unsigned int* Wu = reinterpret_cast<unsigned int*>(S.Wcat);
        Wu[r*(WS/2) + c]      = reinterpret_cast<const unsigned int*>(g_Ad)[i];
        Wu[r*(WS/2) + 64 + c] = reinterpret_cast<const unsigned int*>(g_Ar)[i];
    }
    // ---- stage tables (center terms already packed; rel tables packed here) ----
    for (int i = tid; i < NB*64; i += 576) {
        int n = i >> 6, cp = (i & 63) << 1;
        float2 fd = *reinterpret_cast<const float2*>(&g_relbd[n*HID + cp]);
        float2 fr = *reinterpret_cast<const float2*>(&g_relbr[n*HID + cp]);
        __nv_bfloat162 bd = __floats2bfloat162_rn(fd.x, fd.y);
        __nv_bfloat162 br = __floats2bfloat162_rn(fr.x, fr.y);
        S.Rdu[n*68 + (cp>>1)] = *reinterpret_cast<unsigned int*>(&bd);
        S.Rru[n*68 + (cp>>1)] = *reinterpret_cast<unsigned int*>(&br);
    }
    for (int i = tid; i < TPB*64; i += 576) {
        int t = i >> 6, j = i & 63;
        S.Cdu[t*68 + j] = g_cdu[(size_t)(tokrow0+t)*64 + j];
        S.Cru[t*68 + j] = g_cru[(size_t)(tokrow0+t)*64 + j];
    }
    if (tid < 64) {
        float2 fd = *reinterpret_cast<const float2*>(&dW2[tid*2]);
        __nv_bfloat162 bd = __floats2bfloat162_rn(fd.x, fd.y);
        S.w2du[tid] = *reinterpret_cast<unsigned int*>(&bd);
    } else if (tid < 128) {
        int j = tid - 64;
        float2 fr = *reinterpret_cast<const float2*>(&rW2[j*2]);
        __nv_bfloat162 br = __floats2bfloat162_rn(fr.x, fr.y);
        S.w2ru[j] = *reinterpret_cast<unsigned int*>(&br);
    }

    // ---- gather scrambled neighborhood: Vs[t*9+n][c2] = norm[y+si-1, x+sj-1, c],
    //      where c*9+s = n*128+c2 (torch reshape semantics) ----
    for (int uidx = tid; uidx < TPB*144; uidx += 576) {
        int t = uidx / 144, rem = uidx - t*144;
        int s = rem >> 4, c0 = (rem & 15) << 3;
        int si = s / 3, sj = s - si*3;
        int yy = y + si - 1, xx = x0 + t + sj - 1;
        union { uint4 v; unsigned short h[8]; } pkt;
        if (yy >= 0 && yy < 128 && xx >= 0 && xx < 128) {
            pkt.v = *reinterpret_cast<const uint4*>(
                g_normbf + ((size_t)((b*128+yy)*128+xx))*CC + c0);
        } else {
            pkt.v = make_uint4(0,0,0,0);
        }
        unsigned short* vsrow = reinterpret_cast<unsigned short*>(S.Vs);
        #pragma unroll
        for (int k = 0; k < 8; k++) {
            int p = (c0 + k)*9 + s;
            vsrow[(t*9 + (p >> 7))*136 + (p & 127)] = pkt.h[k];
        }
    }
    __syncthreads();

    // ---- big GEMM: warp = (row-pair rp 0..8, half d/r). 32 rows x 128 cols per warp.
    //      fa preloaded (16 frags), fb double-buffered, shared across both bands.
    //      Epilogue from accumulator fragments, bf16x2 table loads. ----
    {
        const int rp = wid >> 1, half = wid & 1;
        const int row0w = rp * 32;

        wmma::fragment<wmma::matrix_a,16,16,16,bf16,wmma::row_major> fa[2][8];
        #pragma unroll
        for (int bd = 0; bd < 2; bd++)
            #pragma unroll
            for (int kt = 0; kt < 8; kt++)
                wmma::load_matrix_sync(fa[bd][kt], S.Vs + (row0w + bd*16)*136 + kt*16, 136);

        const int g4 = lane >> 2, t4 = lane & 3;
        const int c0l = t4*2;
        int rw[4], tw[4], nw[4];
        #pragma unroll
        for (int i = 0; i < 4; i++) {
            rw[i] = row0w + (i>>1)*16 + (i&1)*8 + g4;   // i = bd*2 + hi
            tw[i] = rw[i] / 9; nw[i] = rw[i] - tw[i]*9;
        }
        const unsigned int* Cu = half ? S.Cru : S.Cdu;
        const unsigned int* Ru = half ? S.Rru : S.Rdu;
        const unsigned int* Wu2 = half ? S.w2ru : S.w2du;
        float psum[4] = {0.f, 0.f, 0.f, 0.f};

        wmma::fragment<wmma::matrix_b,16,16,16,bf16,wmma::row_major> fbuf[2];
        wmma::fragment<wmma::accumulator,16,16,16,float> accA, accB;
        for (int ct = 0; ct < 8; ct++) {
            wmma::fill_fragment(accA, 0.0f);
            wmma::fill_fragment(accB, 0.0f);
            wmma::load_matrix_sync(fbuf[0], S.Wcat + half*128 + ct*16, WS);
            #pragma unroll
            for (int kt = 0; kt < 8; kt++) {
                if (kt < 7)
                    wmma::load_matrix_sync(fbuf[(kt+1)&1], S.Wcat + (kt+1)*16*WS + half*128 + ct*16, WS);
                wmma::mma_sync(accA, fa[0][kt], fbuf[kt&1], accA);
                wmma::mma_sync(accB, fa[1][kt], fbuf[kt&1], accB);
            }
            // cols: cA = ct*16 + c0l, cB = cA + 8 (uint index = col/2)
            const int uA = (ct*16 + c0l) >> 1, uB = uA + 4;
            unsigned int wau = Wu2[uA], wbu = Wu2[uB];
            float2 wvA = __bfloat1622float2(*reinterpret_cast<__nv_bfloat162*>(&wau));
            float2 wvB = __bfloat1622float2(*reinterpret_cast<__nv_bfloat162*>(&wbu));
            #pragma unroll
            for (int idx = 0; idx < 4; idx++) {
                const float* ax = (idx >= 2) ? accB.x : accA.x;
                const int eb = (idx & 1) ? 2 : 0;      // element base for cA
                unsigned int cua = Cu[tw[idx]*68 + uA], cub = Cu[tw[idx]*68 + uB];
                unsigned int rua = Ru[nw[idx]*68 + uA], rub = Ru[nw[idx]*68 + uB];
                float2 cvA = __bfloat1622float2(*reinterpret_cast<__nv_bfloat162*>(&cua));
                float2 cvB = __bfloat1622float2(*reinterpret_cast<__nv_bfloat162*>(&cub));
                float2 rvA = __bfloat1622float2(*reinterpret_cast<__nv_bfloat162*>(&rua));
                float2 rvB = __bfloat1622float2(*reinterpret_cast<__nv_bfloat162*>(&rub));
                psum[idx] += gelu_fast(ax[eb]   + cvA.x + rvA.x) * wvA.x
                           + gelu_fast(ax[eb+1] + cvA.y + rvA.y) * wvA.y
                           + gelu_fast(ax[eb+4] + cvB.x + rvB.x) * wvB.x
                           + gelu_fast(ax[eb+5] + cvB.y + rvB.y) * wvB.y;
            }
        }
        #pragma unroll
        for (int i = 0; i < 4; i++) {
            #pragma unroll
            for (int o = 1; o <= 2; o <<= 1)
                psum[i] += __shfl_xor_sync(0xffffffffu, psum[i], o);
        }
        if (t4 == 0) {
            float b2v = half ? rb2[0] : db2[0];
            float* dst = half ? S.resist : S.drive;
            #pragma unroll
            for (int i = 0; i < 4; i++) dst[rw[i]] = psum[i] + b2v;
        }
    }
    __syncthreads();

    // ---- gate ----
    if (tid < MROW) {
        float gamma = pg[0], lam = pl[0], bias = pb[0];
        float rres = S.resist[tid];
        float sp = (rres > 20.f) ? rres : log1pf(expf(rres));
        float e = gamma * S.drive[tid] / (lam * sp + 1e-6f) + bias;
        e = fminf(fmaxf(e, -3.0f), 3.0f);
        S.gate[tid] = 1.0f / (1.0f + expf(-e));
    }
    __syncthreads();

    // ---- gated neighbor sum -> mv (raw, bf16), gsum/invm folded in ----
    for (int uidx = tid; uidx < TPB*32; uidx += 576) {
        int t2 = uidx >> 5, cq = (uidx & 31) << 2;
        float gts[NB]; float gsm = 0.f;
        #pragma unroll
        for (int n2 = 0; n2 < 9; n2++) { gts[n2] = S.gate[t2*9+n2]; gsm += gts[n2]; }
        float a0=0.f, a1=0.f, a2=0.f, a3=0.f;
        #pragma unroll
        for (int n2 = 0; n2 < 9; n2++) {
            uint2 pk = *reinterpret_cast<const uint2*>(&S.Vs[(t2*9+n2)*136 + cq]);
            float2 v01 = __bfloat1622float2(*reinterpret_cast<__nv_bfloat162*>(&pk.x));
            float2 v23 = __bfloat1622float2(*reinterpret_cast<__nv_bfloat162*>(&pk.y));
            a0 += gts[n2]*v01.x; a1 += gts[n2]*v01.y;
            a2 += gts[n2]*v23.x; a3 += gts[n2]*v23.y;
        }
        uint2 ok;
        __nv_bfloat162 o01 = __floats2bfloat162_rn(a0, a1);
        __nv_bfloat162 o23 = __floats2bfloat162_rn(a2, a3);
        ok.x = *reinterpret_cast<unsigned int*>(&o01);
        ok.y = *reinterpret_cast<unsigned int*>(&o23);
        *reinterpret_cast<uint2*>(&S.mv[t2*136 + cq]) = ok;
        if (cq == 0) {
            S.gsum[t2] = gsm;
            S.invm[t2] = 1.0f / fmaxf(gsm, 1e-6f);
        }
    }
    __syncthreads();   // Vs now dead; alias its space

    bf16*  msg = reinterpret_cast<bf16*>(S.Vs);                     // TPBx136 bf16
    float* Us  = reinterpret_cast<float*>(reinterpret_cast<char*>(S.Vs) + 16384); // TPBx132 f32

    // ---- mv @ vW -> msg (bf16 direct fragment store) ----
    if (wid < 16) {
        int rt = wid >> 3, ctl = wid & 7;
        wmma::fragment<wmma::matrix_a,16,16,16,bf16,wmma::row_major> fa;
        wmma::fragment<wmma::matrix_b,16,16,16,bf16,wmma::row_major> fb;
        wmma::fragment<wmma::accumulator,16,16,16,float> acc;
        wmma::fill_fragment(acc, 0.0f);
        for (int kt = 0; kt < 8; kt++) {
            wmma::load_matrix_sync(fa, S.mv + rt*16*136 + kt*16, 136);
            wmma::load_matrix_sync(fb, g_vWb + kt*16*128 + ctl*16, 128);
            wmma::mma_sync(acc, fa, fb, acc);
        }
        const int g4 = lane >> 2, t4 = lane & 3;
        #pragma unroll
        for (int ee = 0; ee < 8; ee += 2) {
            int rloc = g4 + ((ee & 2) ? 8 : 0);
            int cloc = 2*t4 + ((ee & 4) ? 8 : 0);
            __nv_bfloat162 pr = __floats2bfloat162_rn(acc.x[ee], acc.x[ee+1]);
            *reinterpret_cast<__nv_bfloat162*>(
                &msg[(rt*16 + rloc)*136 + ctl*16 + cloc]) = pr;
        }
    }
    __syncthreads();
    // ---- msg @ oW -> Us (raw) ----
    if (wid < 16) {
        int rt = wid >> 3, ctl = wid & 7;
        wmma::fragment<wmma::matrix_a,16,16,16,bf16,wmma::row_major> fa;
        wmma::fragment<wmma::matrix_b,16,16,16,bf16,wmma::row_major> fb;
        wmma::fragment<wmma::accumulator,16,16,16,float> acc;
        wmma::fill_fragment(acc, 0.0f);
        for (int kt = 0; kt < 8; kt++) {
            wmma::load_matrix_sync(fa, msg + rt*16*136 + kt*16, 136);
            wmma::load_matrix_sync(fb, g_oWb + kt*16*128 + ctl*16, 128);
            wmma::mma_sync(acc, fa, fb, acc);
        }
        wmma::store_matrix_sync(Us + rt*16*132 + ctl*16, acc, 132, wmma::mem_row_major);
    }
    __syncthreads();
    // ---- LN2(tokens + invm*Us + invm*gsum*vbo + ob) ----
    for (int r = wid; r < TPB; r += 18) {
        size_t grow = (size_t)(tokrow0 + r) * CC;
        float im = S.invm[r], gs = S.gsum[r] * im;
        float4 tv = reinterpret_cast<const float4*>(tokens + grow)[lane];
        float4 uv = *reinterpret_cast<const float4*>(&Us[r*132 + 4*lane]);
        float4 ov = reinterpret_cast<const float4*>(ob)[lane];
        float4 bv = reinterpret_cast<const float4*>(g_vbo)[lane];
        float v0 = tv.x + uv.x*im + gs*bv.x + ov.x;
        float v1 = tv.y + uv.y*im + gs*bv.y + ov.y;
        float v2 = tv.z + uv.z*im + gs*bv.z + ov.z;
        float v3 = tv.w + uv.w*im + gs*bv.w + ov.w;
        float s = v0+v1+v2+v3;
        #pragma unroll
        for (int o = 16; o; o >>= 1) s += __shfl_xor_sync(0xffffffffu, s, o);
        float mean = s * (1.0f/128.0f);
        float d0=v0-mean, d1=v1-mean, d2=v2-mean, d3=v3-mean;
        float q = d0*d0+d1*d1+d2*d2+d3*d3;
        #pragma unroll
        for (int o = 16; o; o >>= 1) q += __shfl_xor_sync(0xffffffffu, q, o);
        float rstd = rsqrtf(q * (1.0f/128.0f) + 1e-5f);
        float4 gg = reinterpret_cast<const float4*>(ln2g)[lane];
        float4 bb = reinterpret_cast<const float4*>(ln2b)[lane];
        float4 o4;
        o4.x = d0*rstd*gg.x+bb.x; o4.y = d1*rstd*gg.y+bb.y;
        o4.z = d2*rstd*gg.z+bb.z; o4.w = d3*rstd*gg.w+bb.w;
        reinterpret_cast<float4*>(out + grow)[lane] = o4;
    }
}

// ================= launch =================
extern "C" void kernel_launch(void* const* d_in, const int* in_sizes, int n_in,
                              void* d_out, int out_size)
{
    const float* tokens = (const float*)d_in[0];
    const float* ln1g   = (const float*)d_in[1];
    const float* ln1b   = (const float*)d_in[2];
    const float* ln2g   = (const float*)d_in[3];
    const float* ln2b   = (const float*)d_in[4];
    const float* relp   = (const float*)d_in[5];
    const float* dW1    = (const float*)d_in[6];
    const float* db1    = (const float*)d_in[7];
    const float* dW2    = (const float*)d_in[8];
    const float* db2    = (const float*)d_in[9];
    const float* rW1    = (const float*)d_in[10];
    const float* rb1    = (const float*)d_in[11];
    const float* rW2    = (const float*)d_in[12];
    const float* rb2    = (const float*)d_in[13];
    const float* vW     = (const float*)d_in[14];
    const float* vb     = (const float*)d_in[15];
    const float* oW     = (const float*)d_in[16];
    const float* ob     = (const float*)d_in[17];
    const float* pg     = (const float*)d_in[18];
    const float* pl     = (const float*)d_in[19];
    const float* pb     = (const float*)d_in[20];
    float* out = (float*)d_out;

    static_assert(sizeof(SmemMain) <= 200000, "smem too big");
    cudaFuncSetAttribute(k_center, cudaFuncAttributeMaxDynamicSharedMemorySize, CSMEM);
    cudaFuncSetAttribute(k_main, cudaFuncAttributeMaxDynamicSharedMemorySize, (int)sizeof(SmemMain));

    k_prep<<<64, 256>>>(dW1, rW1, vW, oW, relp, db1, rb1);
    k_vbo<<<32, 128>>>(vb, oW);
    dim3 cgrid(256, 2);
    k_center<<<cgrid, 256, CSMEM>>>(tokens, ln1g, ln1b);
    k_main<<<1024, 576, sizeof(SmemMain)>>>(tokens, ln2g, ln2b, dW2, db2, rW2, rb2,
                                            ob, pg, pl, pb, out);
}